// round 8
// baseline (speedup 1.0000x reference)
#include <cuda_runtime.h>
#include <cuda_fp16.h>
#include <math.h>
#include <stdint.h>

#define B_   4
#define T_   2048
#define D_   1024
#define H_   16
#define DH_  64
#define NTOK (B_ * T_)          // 8192
#define QKV_COLS (3 * D_)       // 3072

// ---------------------------------------------------------------------------
// fp16 global scratch (allocation-free rule: __device__ globals)
// ---------------------------------------------------------------------------
__device__ __half g_x_h[(size_t)NTOK * D_];
__device__ __half g_wqkv_h[(size_t)QKV_COLS * D_];
__device__ __half g_wout_h[(size_t)D_ * D_];
__device__ __half g_qkv_h[(size_t)NTOK * QKV_COLS];
__device__ __half g_attn_h[(size_t)NTOK * D_];

// ---------------------------------------------------------------------------
// helpers
// ---------------------------------------------------------------------------
__device__ __forceinline__ uint32_t su32(const void* p) {
    return (uint32_t)__cvta_generic_to_shared(p);
}
__device__ __forceinline__ void ldsm4(uint32_t* r, uint32_t a) {
    asm volatile("ldmatrix.sync.aligned.m8n8.x4.shared.b16 {%0,%1,%2,%3}, [%4];"
        : "=r"(r[0]), "=r"(r[1]), "=r"(r[2]), "=r"(r[3]) : "r"(a));
}
__device__ __forceinline__ void ldsm4t(uint32_t* r, uint32_t a) {
    asm volatile("ldmatrix.sync.aligned.m8n8.x4.trans.shared.b16 {%0,%1,%2,%3}, [%4];"
        : "=r"(r[0]), "=r"(r[1]), "=r"(r[2]), "=r"(r[3]) : "r"(a));
}
__device__ __forceinline__ void mmaf16(float* c, const uint32_t* a,
                                       uint32_t b0, uint32_t b1) {
    asm volatile(
        "mma.sync.aligned.m16n8k16.row.col.f32.f16.f16.f32 "
        "{%0,%1,%2,%3},{%4,%5,%6,%7},{%8,%9},{%0,%1,%2,%3};"
        : "+f"(c[0]), "+f"(c[1]), "+f"(c[2]), "+f"(c[3])
        : "r"(a[0]), "r"(a[1]), "r"(a[2]), "r"(a[3]), "r"(b0), "r"(b1));
}
__device__ __forceinline__ uint32_t pkh(float x, float y) {
    __half2 t = __floats2half2_rn(x, y);
    return *reinterpret_cast<uint32_t*>(&t);
}
__device__ __forceinline__ float ex2(float x) {
    float r;
    asm("ex2.approx.f32 %0, %1;" : "=f"(r) : "f"(x));
    return r;
}
__device__ __forceinline__ void cpa16(uint32_t s, const void* g) {
    asm volatile("cp.async.cg.shared.global [%0], [%1], 16;" :: "r"(s), "l"(g));
}
#define CP_COMMIT() asm volatile("cp.async.commit_group;" ::: "memory")
#define CP_WAIT(n)  asm volatile("cp.async.wait_group %0;" :: "n"(n) : "memory")

// ---------------------------------------------------------------------------
// presingle: fp32 -> fp16
// ---------------------------------------------------------------------------
__global__ void presingle(const float* __restrict__ in, __half* __restrict__ hi, int n4)
{
    int i = blockIdx.x * blockDim.x + threadIdx.x;
    const int stride = gridDim.x * blockDim.x;
    for (; i < n4; i += stride) {
        float4 v = ((const float4*)in)[i];
        ((uint2*)hi)[i] = make_uint2(pkh(v.x, v.y), pkh(v.z, v.w));
    }
}

// ---------------------------------------------------------------------------
// fp16 GEMM: C[M,Ntot] = A * Bw^T + bias
// BM=BN=128, BK=32, 128 threads (4 warps 2x2, warp tile 64x64).
// 4-stage cp.async pipeline; 8 LDSM feed 32 MMAs per kk (ratio 4).
// ---------------------------------------------------------------------------
#define GST 40                       // smem row stride in fp16 (80 bytes)
#define GARR (128 * GST * 2)         // 10240 bytes per array
#define GSTAGE (2 * GARR)            // 20480 bytes per stage
#define NSTG 4

template<bool WRITE_HALF>
__global__ __launch_bounds__(128, 2)
void gemm_f16(const __half* __restrict__ Ahg, const __half* __restrict__ Bhg,
              const float* __restrict__ bias,
              float* __restrict__ Cf, __half* __restrict__ Ch, int Ntot, int K)
{
    extern __shared__ char dsm[];

    const int tid = threadIdx.x, lane = tid & 31, wid = tid >> 5;
    const int wm = wid & 1, wn = wid >> 1;
    const int row0 = blockIdx.y * 128, col0 = blockIdx.x * 128;

    float acc[4][8][4];
#pragma unroll
    for (int mt = 0; mt < 4; mt++)
#pragma unroll
        for (int nt = 0; nt < 8; nt++)
#pragma unroll
            for (int i = 0; i < 4; i++) acc[mt][nt][i] = 0.f;

    auto prefetch = [&](int it) {
        char* base = dsm + (it & (NSTG - 1)) * GSTAGE;
#pragma unroll
        for (int i = 0; i < 4; i++) {
            const int id = tid + i * 128;        // 0..511
            const int r = id >> 2, c = id & 3;
            const uint32_t so = r * 80 + c * 16;
            cpa16(su32(base + so),        Ahg + (size_t)(row0 + r) * K + it * 32 + c * 8);
            cpa16(su32(base + GARR + so), Bhg + (size_t)(col0 + r) * K + it * 32 + c * 8);
        }
    };

    const int nit = K / 32;
#pragma unroll
    for (int it = 0; it < NSTG - 1; it++) { prefetch(it); CP_COMMIT(); }

    const int la = (lane & 15) * GST + ((lane >> 4) << 3);

    for (int it = 0; it < nit; it++) {
        CP_WAIT(NSTG - 2);
        __syncthreads();
        if (it + NSTG - 1 < nit) prefetch(it + NSTG - 1);
        CP_COMMIT();

        const __half* sA = (const __half*)(dsm + (it & (NSTG - 1)) * GSTAGE);
        const __half* sB = (const __half*)(dsm + (it & (NSTG - 1)) * GSTAGE + GARR);
        const uint32_t aw = su32(sA + wm * 64 * GST + la);
        const uint32_t bw = su32(sB + wn * 64 * GST + la);

#pragma unroll
        for (int kk = 0; kk < 2; kk++) {
            const uint32_t co = kk * 32;         // 16 halfs = 32 bytes
            uint32_t ah[4][4], bh[4][4];
#pragma unroll
            for (int t = 0; t < 4; t++)
                ldsm4(ah[t], aw + t * 16 * GST * 2 + co);
#pragma unroll
            for (int t = 0; t < 4; t++)
                ldsm4(bh[t], bw + t * 16 * GST * 2 + co);
#pragma unroll
            for (int mt = 0; mt < 4; mt++)
#pragma unroll
                for (int np = 0; np < 4; np++) {
                    mmaf16(acc[mt][np * 2],     ah[mt], bh[np][0], bh[np][2]);
                    mmaf16(acc[mt][np * 2 + 1], ah[mt], bh[np][1], bh[np][3]);
                }
        }
    }

    // epilogue
    const int g = lane >> 2, tq = lane & 3;
#pragma unroll
    for (int mt = 0; mt < 4; mt++) {
        const int r = row0 + wm * 64 + mt * 16 + g;
#pragma unroll
        for (int nt = 0; nt < 8; nt++) {
            const int c = col0 + wn * 64 + nt * 8 + tq * 2;
            float2 bi = *(const float2*)(bias + c);
            const float f0 = acc[mt][nt][0] + bi.x, f1 = acc[mt][nt][1] + bi.y;
            const float f2 = acc[mt][nt][2] + bi.x, f3 = acc[mt][nt][3] + bi.y;
            if (WRITE_HALF) {
                *(uint32_t*)&Ch[(size_t)r * Ntot + c]       = pkh(f0, f1);
                *(uint32_t*)&Ch[(size_t)(r + 8) * Ntot + c] = pkh(f2, f3);
            } else {
                *(float2*)(Cf + (size_t)r * Ntot + c)       = make_float2(f0, f1);
                *(float2*)(Cf + (size_t)(r + 8) * Ntot + c) = make_float2(f2, f3);
            }
        }
    }
}

// ---------------------------------------------------------------------------
// Flash attention, fp16, base-2 softmax, fragment-pipelined MMA loops.
// 256 threads (8 warps), 128 q-rows per block, one (b,h).  (unchanged R7)
// ---------------------------------------------------------------------------
#define AST 72
#define AARR (128 * AST * 2)   // 18432 bytes per array
#define C2   0.1803368801f     // (1/sqrt(64)) * log2(e)

__global__ __launch_bounds__(256, 2)
void attn_f16(const __half* __restrict__ qkvh, __half* __restrict__ attnh)
{
    extern __shared__ char dsm[];
    __half* Kh = (__half*)dsm;

    const int tid = threadIdx.x, lane = tid & 31, wid = tid >> 5;
    const int b = blockIdx.y >> 4, h = blockIdx.y & 15;
    const int q0 = blockIdx.x * 128;

    const size_t hb = (size_t)b * T_ * QKV_COLS + h * DH_;
    const __half* qbh = qkvh + hb;
    const __half* kbh = qbh + D_;
    const __half* vbh = qbh + 2 * D_;

    auto loadTile = [&](const __half* src, char* dstbase, int row_off) {
#pragma unroll
        for (int i = 0; i < 4; i++) {
            const int id = tid + i * 256;
            const int r = id >> 3, c = id & 7;
            const uint32_t so = r * 144 + c * 16;
            const size_t g = (size_t)(row_off + r) * QKV_COLS + c * 8;
            cpa16(su32(dstbase + so), src + g);
        }
    };

    // ---- stage Q, pull fragments ----
    loadTile(qbh, dsm, q0);
    CP_COMMIT(); CP_WAIT(0); __syncthreads();

    uint32_t qh[4][4];
#pragma unroll
    for (int kc = 0; kc < 4; kc++) {
        const int rw = wid * 16 + (lane & 15);
        const int cl = kc * 16 + ((lane >> 4) << 3);
        ldsm4(qh[kc], su32(&Kh[rw * AST + cl]));
    }
    __syncthreads();

    loadTile(kbh, dsm, 0);
    loadTile(vbh, dsm + AARR, 0);
    CP_COMMIT(); CP_WAIT(0); __syncthreads();

    float oacc[8][4];
#pragma unroll
    for (int nt = 0; nt < 8; nt++)
#pragma unroll
        for (int i = 0; i < 4; i++) oacc[nt][i] = 0.f;
    float mr0 = -1e30f, mr1 = -1e30f, lr0 = 0.f, lr1 = 0.f;

    const uint32_t kla = (lane & 15) * AST * 2 + ((lane >> 4) << 3) * 2;
    const uint32_t vla = ((lane & 7) + ((lane >> 3) & 1) * 8) * AST * 2 +
                         ((lane >> 4) << 3) * 2;

    for (int kt = 0; kt < 16; kt++) {
        const int vs = kt & 1;

        // ---- S = Q K^T ----
        float sacc[16][4];
#pragma unroll
        for (int nt = 0; nt < 16; nt++)
#pragma unroll
            for (int i = 0; i < 4; i++) sacc[nt][i] = 0.f;

        {
            const uint32_t kb0 = su32(Kh) + kla;
            uint32_t kb[2][4];
            ldsm4(kb[0], kb0);
#pragma unroll
            for (int idx = 0; idx < 32; idx++) {
                const int np = idx >> 2, kc = idx & 3;
                const int cur = idx & 1;
                if (idx < 31) {
                    const int np1 = (idx + 1) >> 2, kc1 = (idx + 1) & 3;
                    ldsm4(kb[cur ^ 1], kb0 + np1 * 16 * AST * 2 + kc1 * 32);
                }
                mmaf16(sacc[np * 2],     qh[kc], kb[cur][0], kb[cur][2]);
                mmaf16(sacc[np * 2 + 1], qh[kc], kb[cur][1], kb[cur][3]);
            }
        }
        __syncthreads();
        if (kt < 15) {
            loadTile(kbh, dsm, (kt + 1) * 128);
            loadTile(vbh, dsm + AARR + (vs ^ 1) * AARR, (kt + 1) * 128);
            CP_COMMIT();
        }

        // ---- online softmax (base-2 units) ----
        float tm0 = -1e30f, tm1 = -1e30f;
#pragma unroll
        for (int nt = 0; nt < 16; nt++) {
            tm0 = fmaxf(tm0, fmaxf(sacc[nt][0], sacc[nt][1]));
            tm1 = fmaxf(tm1, fmaxf(sacc[nt][2], sacc[nt][3]));
        }
        tm0 = fmaxf(tm0, __shfl_xor_sync(0xffffffffu, tm0, 1));
        tm0 = fmaxf(tm0, __shfl_xor_sync(0xffffffffu, tm0, 2));
        tm1 = fmaxf(tm1, __shfl_xor_sync(0xffffffffu, tm1, 1));
        tm1 = fmaxf(tm1, __shfl_xor_sync(0xffffffffu, tm1, 2));

        const float nm0 = fmaxf(mr0, tm0 * C2);
        const float nm1 = fmaxf(mr1, tm1 * C2);
        const float al0 = ex2(mr0 - nm0);
        const float al1 = ex2(mr1 - nm1);
        mr0 = nm0; mr1 = nm1;
#pragma unroll
        for (int nt = 0; nt < 8; nt++) {
            oacc[nt][0] *= al0; oacc[nt][1] *= al0;
            oacc[nt][2] *= al1; oacc[nt][3] *= al1;
        }

        float rs0 = 0.f, rs1 = 0.f;
        uint32_t php[8][4];
#pragma unroll
        for (int j = 0; j < 8; j++) {
            const float p00 = ex2(fmaf(sacc[2 * j][0],     C2, -nm0));
            const float p01 = ex2(fmaf(sacc[2 * j][1],     C2, -nm0));
            const float p10 = ex2(fmaf(sacc[2 * j][2],     C2, -nm1));
            const float p11 = ex2(fmaf(sacc[2 * j][3],     C2, -nm1));
            const float r00 = ex2(fmaf(sacc[2 * j + 1][0], C2, -nm0));
            const float r01 = ex2(fmaf(sacc[2 * j + 1][1], C2, -nm0));
            const float r10 = ex2(fmaf(sacc[2 * j + 1][2], C2, -nm1));
            const float r11 = ex2(fmaf(sacc[2 * j + 1][3], C2, -nm1));
            rs0 += (p00 + p01) + (r00 + r01);
            rs1 += (p10 + p11) + (r10 + r11);
            php[j][0] = pkh(p00, p01);
            php[j][1] = pkh(p10, p11);
            php[j][2] = pkh(r00, r01);
            php[j][3] = pkh(r10, r11);
        }
        rs0 += __shfl_xor_sync(0xffffffffu, rs0, 1);
        rs0 += __shfl_xor_sync(0xffffffffu, rs0, 2);
        rs1 += __shfl_xor_sync(0xffffffffu, rs1, 1);
        rs1 += __shfl_xor_sync(0xffffffffu, rs1, 2);
        lr0 = lr0 * al0 + rs0;
        lr1 = lr1 * al1 + rs1;

        // ---- O += P V ----
        {
            const uint32_t vb0 = su32(dsm + AARR + vs * AARR) + vla;
            uint32_t vb[2][4];
            ldsm4t(vb[0], vb0);
#pragma unroll
            for (int idx = 0; idx < 32; idx++) {
                const int j = idx >> 2, dp = idx & 3;
                const int cur = idx & 1;
                if (idx < 31) {
                    const int j1 = (idx + 1) >> 2, dp1 = (idx + 1) & 3;
                    ldsm4t(vb[cur ^ 1], vb0 + j1 * 16 * AST * 2 + dp1 * 32);
                }
                mmaf16(oacc[dp * 2],     php[j], vb[cur][0], vb[cur][1]);
                mmaf16(oacc[dp * 2 + 1], php[j], vb[cur][2], vb[cur][3]);
            }
        }

        if (kt < 15) { CP_WAIT(0); __syncthreads(); }
    }

    // ---- epilogue: normalize, store fp16 ----
    const float inv0 = 1.f / lr0, inv1 = 1.f / lr1;
    const int g = lane >> 2, tq = lane & 3;
    const size_t r0o = (size_t)(b * T_ + q0 + wid * 16 + g);
#pragma unroll
    for (int nt = 0; nt < 8; nt++) {
        const int col = h * DH_ + nt * 8 + tq * 2;
        *(uint32_t*)&attnh[r0o * D_ + col] =
            pkh(oacc[nt][0] * inv0, oacc[nt][1] * inv0);
        *(uint32_t*)&attnh[(r0o + 8) * D_ + col] =
            pkh(oacc[nt][2] * inv1, oacc[nt][3] * inv1);
    }
}

// ---------------------------------------------------------------------------
// kernel_launch
// ---------------------------------------------------------------------------
extern "C" void kernel_launch(void* const* d_in, const int* in_sizes, int n_in,
                              void* d_out, int out_size)
{
    const float* x     = (const float*)d_in[0];
    const float* w_qkv = (const float*)d_in[1];
    const float* b_qkv = (const float*)d_in[2];
    const float* w_out = (const float*)d_in[3];
    const float* b_out = (const float*)d_in[4];
    float* out = (float*)d_out;

    __half *xh, *wqh, *woh, *qh, *ah;
    cudaGetSymbolAddress((void**)&xh,  g_x_h);
    cudaGetSymbolAddress((void**)&wqh, g_wqkv_h);
    cudaGetSymbolAddress((void**)&woh, g_wout_h);
    cudaGetSymbolAddress((void**)&qh,  g_qkv_h);
    cudaGetSymbolAddress((void**)&ah,  g_attn_h);

    // 0) round inputs to fp16
    presingle<<<1024, 256>>>(x,     xh,  NTOK * D_ / 4);
    presingle<<<1024, 256>>>(w_qkv, wqh, QKV_COLS * D_ / 4);
    presingle<<<512,  256>>>(w_out, woh, D_ * D_ / 4);

    const int gsmem = NSTG * GSTAGE;  // 81920
    cudaFuncSetAttribute(gemm_f16<true>,
                         cudaFuncAttributeMaxDynamicSharedMemorySize, gsmem);
    cudaFuncSetAttribute(gemm_f16<false>,
                         cudaFuncAttributeMaxDynamicSharedMemorySize, gsmem);

    // 1) QKV projection -> fp16
    {
        dim3 grid(QKV_COLS / 128, NTOK / 128);
        gemm_f16<true><<<grid, 128, gsmem>>>(xh, wqh, b_qkv,
                                             nullptr, qh, QKV_COLS, D_);
    }

    // 2) Flash attention -> fp16
    {
        const int asmem = 3 * AARR;  // 55296
        cudaFuncSetAttribute(attn_f16,
                             cudaFuncAttributeMaxDynamicSharedMemorySize, asmem);
        dim3 grid(T_ / 128, B_ * H_);
        attn_f16<<<grid, 256, asmem>>>(qh, ah);
    }

    // 3) Output projection -> fp32
    {
        dim3 grid(D_ / 128, NTOK / 128);
        gemm_f16<false><<<grid, 128, gsmem>>>(ah, woh, b_out,
                                              out, nullptr, D_, D_);
    }
}

// round 9
// speedup vs baseline: 1.1265x; 1.1265x over previous
#include <cuda_runtime.h>
#include <cuda_fp16.h>
#include <math.h>
#include <stdint.h>

#define B_   4
#define T_   2048
#define D_   1024
#define H_   16
#define DH_  64
#define NTOK (B_ * T_)          // 8192
#define QKV_COLS (3 * D_)       // 3072

// ---------------------------------------------------------------------------
// fp16 global scratch (allocation-free rule: __device__ globals)
// ---------------------------------------------------------------------------
__device__ __half g_x_h[(size_t)NTOK * D_];
__device__ __half g_wqkv_h[(size_t)QKV_COLS * D_];
__device__ __half g_wout_h[(size_t)D_ * D_];
__device__ __half g_qkv_h[(size_t)NTOK * QKV_COLS];
__device__ __half g_attn_h[(size_t)NTOK * D_];

// ---------------------------------------------------------------------------
// helpers
// ---------------------------------------------------------------------------
__device__ __forceinline__ uint32_t su32(const void* p) {
    return (uint32_t)__cvta_generic_to_shared(p);
}
__device__ __forceinline__ void ldsm4(uint32_t* r, uint32_t a) {
    asm volatile("ldmatrix.sync.aligned.m8n8.x4.shared.b16 {%0,%1,%2,%3}, [%4];"
        : "=r"(r[0]), "=r"(r[1]), "=r"(r[2]), "=r"(r[3]) : "r"(a));
}
__device__ __forceinline__ void ldsm4t(uint32_t* r, uint32_t a) {
    asm volatile("ldmatrix.sync.aligned.m8n8.x4.trans.shared.b16 {%0,%1,%2,%3}, [%4];"
        : "=r"(r[0]), "=r"(r[1]), "=r"(r[2]), "=r"(r[3]) : "r"(a));
}
__device__ __forceinline__ void mmaf16(float* c, const uint32_t* a,
                                       uint32_t b0, uint32_t b1) {
    asm volatile(
        "mma.sync.aligned.m16n8k16.row.col.f32.f16.f16.f32 "
        "{%0,%1,%2,%3},{%4,%5,%6,%7},{%8,%9},{%0,%1,%2,%3};"
        : "+f"(c[0]), "+f"(c[1]), "+f"(c[2]), "+f"(c[3])
        : "r"(a[0]), "r"(a[1]), "r"(a[2]), "r"(a[3]), "r"(b0), "r"(b1));
}
__device__ __forceinline__ uint32_t pkh(float x, float y) {
    __half2 t = __floats2half2_rn(x, y);
    return *reinterpret_cast<uint32_t*>(&t);
}
__device__ __forceinline__ float ex2(float x) {
    float r;
    asm("ex2.approx.f32 %0, %1;" : "=f"(r) : "f"(x));
    return r;
}
__device__ __forceinline__ void cpa16(uint32_t s, const void* g) {
    asm volatile("cp.async.cg.shared.global [%0], [%1], 16;" :: "r"(s), "l"(g));
}
#define CP_COMMIT() asm volatile("cp.async.commit_group;" ::: "memory")
#define CP_WAIT(n)  asm volatile("cp.async.wait_group %0;" :: "n"(n) : "memory")

// ---------------------------------------------------------------------------
// presingle: fp32 -> fp16
// ---------------------------------------------------------------------------
__global__ void presingle(const float* __restrict__ in, __half* __restrict__ hi, int n4)
{
    int i = blockIdx.x * blockDim.x + threadIdx.x;
    const int stride = gridDim.x * blockDim.x;
    for (; i < n4; i += stride) {
        float4 v = ((const float4*)in)[i];
        ((uint2*)hi)[i] = make_uint2(pkh(v.x, v.y), pkh(v.z, v.w));
    }
}

// ---------------------------------------------------------------------------
// fp16 GEMM: C[M,Ntot] = A * Bw^T + bias
// BM=BN=128, BK=32, 128 threads (4 warps 2x2, warp tile 64x64).
// 4-stage cp.async pipeline; fragments double-buffered a FULL kk (16 MMA
// distance) ahead, including across the stage-advance syncthreads.
// ---------------------------------------------------------------------------
#define GST 40                       // smem row stride in fp16 (80 bytes)
#define GARR (128 * GST * 2)         // 10240 bytes per array
#define GSTAGE (2 * GARR)            // 20480 bytes per stage
#define NSTG 4

template<bool WRITE_HALF>
__global__ __launch_bounds__(128, 2)
void gemm_f16(const __half* __restrict__ Ahg, const __half* __restrict__ Bhg,
              const float* __restrict__ bias,
              float* __restrict__ Cf, __half* __restrict__ Ch, int Ntot, int K)
{
    extern __shared__ char dsm[];

    const int tid = threadIdx.x, lane = tid & 31, wid = tid >> 5;
    const int wm = wid & 1, wn = wid >> 1;
    const int row0 = blockIdx.y * 128, col0 = blockIdx.x * 128;

    float acc[4][8][4];
#pragma unroll
    for (int mt = 0; mt < 4; mt++)
#pragma unroll
        for (int nt = 0; nt < 8; nt++)
#pragma unroll
            for (int i = 0; i < 4; i++) acc[mt][nt][i] = 0.f;

    auto prefetch = [&](int it) {
        char* base = dsm + (it & (NSTG - 1)) * GSTAGE;
#pragma unroll
        for (int i = 0; i < 4; i++) {
            const int id = tid + i * 128;        // 0..511
            const int r = id >> 2, c = id & 3;
            const uint32_t so = r * 80 + c * 16;
            cpa16(su32(base + so),        Ahg + (size_t)(row0 + r) * K + it * 32 + c * 8);
            cpa16(su32(base + GARR + so), Bhg + (size_t)(col0 + r) * K + it * 32 + c * 8);
        }
    };

    const int nit = K / 32;
#pragma unroll
    for (int it = 0; it < NSTG - 1; it++) { prefetch(it); CP_COMMIT(); }

    // byte offset of this lane's ldsm base within a tile array
    const uint32_t la = ((lane & 15) * GST + ((lane >> 4) << 3)) * 2;
    const uint32_t awo = wm * 64 * GST * 2 + la;           // A: warp row block
    const uint32_t bwo = GARR + wn * 64 * GST * 2 + la;    // B: warp col block

    CP_WAIT(NSTG - 2);
    __syncthreads();

    uint32_t fa[2][4][4], fb[2][4][4];
    // F0 <- (it=0, kk=0)
    {
        const uint32_t sbase = su32(dsm);   // stage 0
#pragma unroll
        for (int t = 0; t < 4; t++) ldsm4(fa[0][t], sbase + awo + t * 16 * GST * 2);
#pragma unroll
        for (int t = 0; t < 4; t++) ldsm4(fb[0][t], sbase + bwo + t * 16 * GST * 2);
    }

    for (int it = 0; it < nit; it++) {
        const uint32_t sbase = su32(dsm + (it & (NSTG - 1)) * GSTAGE);

        // F1 <- (it, kk=1); latency covered by the 32 MMAs on F0 below
#pragma unroll
        for (int t = 0; t < 4; t++) ldsm4(fa[1][t], sbase + awo + t * 16 * GST * 2 + 32);
#pragma unroll
        for (int t = 0; t < 4; t++) ldsm4(fb[1][t], sbase + bwo + t * 16 * GST * 2 + 32);

#pragma unroll
        for (int mt = 0; mt < 4; mt++)
#pragma unroll
            for (int np = 0; np < 4; np++) {
                mmaf16(acc[mt][np * 2],     fa[0][mt], fb[0][np][0], fb[0][np][2]);
                mmaf16(acc[mt][np * 2 + 1], fa[0][mt], fb[0][np][1], fb[0][np][3]);
            }

        if (it + NSTG - 1 < nit) prefetch(it + NSTG - 1);
        CP_COMMIT();
        CP_WAIT(NSTG - 2);
        __syncthreads();

        // F0 <- (it+1, kk=0); latency covered by the 32 MMAs on F1 below
        if (it + 1 < nit) {
            const uint32_t sb2 = su32(dsm + ((it + 1) & (NSTG - 1)) * GSTAGE);
#pragma unroll
            for (int t = 0; t < 4; t++) ldsm4(fa[0][t], sb2 + awo + t * 16 * GST * 2);
#pragma unroll
            for (int t = 0; t < 4; t++) ldsm4(fb[0][t], sb2 + bwo + t * 16 * GST * 2);
        }

#pragma unroll
        for (int mt = 0; mt < 4; mt++)
#pragma unroll
            for (int np = 0; np < 4; np++) {
                mmaf16(acc[mt][np * 2],     fa[1][mt], fb[1][np][0], fb[1][np][2]);
                mmaf16(acc[mt][np * 2 + 1], fa[1][mt], fb[1][np][1], fb[1][np][3]);
            }
    }

    // epilogue
    const int g = lane >> 2, tq = lane & 3;
#pragma unroll
    for (int mt = 0; mt < 4; mt++) {
        const int r = row0 + wm * 64 + mt * 16 + g;
#pragma unroll
        for (int nt = 0; nt < 8; nt++) {
            const int c = col0 + wn * 64 + nt * 8 + tq * 2;
            float2 bi = *(const float2*)(bias + c);
            const float f0 = acc[mt][nt][0] + bi.x, f1 = acc[mt][nt][1] + bi.y;
            const float f2 = acc[mt][nt][2] + bi.x, f3 = acc[mt][nt][3] + bi.y;
            if (WRITE_HALF) {
                *(uint32_t*)&Ch[(size_t)r * Ntot + c]       = pkh(f0, f1);
                *(uint32_t*)&Ch[(size_t)(r + 8) * Ntot + c] = pkh(f2, f3);
            } else {
                *(float2*)(Cf + (size_t)r * Ntot + c)       = make_float2(f0, f1);
                *(float2*)(Cf + (size_t)(r + 8) * Ntot + c) = make_float2(f2, f3);
            }
        }
    }
}

// ---------------------------------------------------------------------------
// Flash attention, fp16, base-2 softmax (unchanged from R7).
// 256 threads (8 warps), 128 q-rows per block, one (b,h).
// ---------------------------------------------------------------------------
#define AST 72
#define AARR (128 * AST * 2)   // 18432 bytes per array
#define C2   0.1803368801f     // (1/sqrt(64)) * log2(e)

__global__ __launch_bounds__(256, 2)
void attn_f16(const __half* __restrict__ qkvh, __half* __restrict__ attnh)
{
    extern __shared__ char dsm[];
    __half* Kh = (__half*)dsm;

    const int tid = threadIdx.x, lane = tid & 31, wid = tid >> 5;
    const int b = blockIdx.y >> 4, h = blockIdx.y & 15;
    const int q0 = blockIdx.x * 128;

    const size_t hb = (size_t)b * T_ * QKV_COLS + h * DH_;
    const __half* qbh = qkvh + hb;
    const __half* kbh = qbh + D_;
    const __half* vbh = qbh + 2 * D_;

    auto loadTile = [&](const __half* src, char* dstbase, int row_off) {
#pragma unroll
        for (int i = 0; i < 4; i++) {
            const int id = tid + i * 256;
            const int r = id >> 3, c = id & 7;
            const uint32_t so = r * 144 + c * 16;
            const size_t g = (size_t)(row_off + r) * QKV_COLS + c * 8;
            cpa16(su32(dstbase + so), src + g);
        }
    };

    // ---- stage Q, pull fragments ----
    loadTile(qbh, dsm, q0);
    CP_COMMIT(); CP_WAIT(0); __syncthreads();

    uint32_t qh[4][4];
#pragma unroll
    for (int kc = 0; kc < 4; kc++) {
        const int rw = wid * 16 + (lane & 15);
        const int cl = kc * 16 + ((lane >> 4) << 3);
        ldsm4(qh[kc], su32(&Kh[rw * AST + cl]));
    }
    __syncthreads();

    loadTile(kbh, dsm, 0);
    loadTile(vbh, dsm + AARR, 0);
    CP_COMMIT(); CP_WAIT(0); __syncthreads();

    float oacc[8][4];
#pragma unroll
    for (int nt = 0; nt < 8; nt++)
#pragma unroll
        for (int i = 0; i < 4; i++) oacc[nt][i] = 0.f;
    float mr0 = -1e30f, mr1 = -1e30f, lr0 = 0.f, lr1 = 0.f;

    const uint32_t kla = (lane & 15) * AST * 2 + ((lane >> 4) << 3) * 2;
    const uint32_t vla = ((lane & 7) + ((lane >> 3) & 1) * 8) * AST * 2 +
                         ((lane >> 4) << 3) * 2;

    for (int kt = 0; kt < 16; kt++) {
        const int vs = kt & 1;

        // ---- S = Q K^T ----
        float sacc[16][4];
#pragma unroll
        for (int nt = 0; nt < 16; nt++)
#pragma unroll
            for (int i = 0; i < 4; i++) sacc[nt][i] = 0.f;

        {
            const uint32_t kb0 = su32(Kh) + kla;
            uint32_t kb[2][4];
            ldsm4(kb[0], kb0);
#pragma unroll
            for (int idx = 0; idx < 32; idx++) {
                const int np = idx >> 2, kc = idx & 3;
                const int cur = idx & 1;
                if (idx < 31) {
                    const int np1 = (idx + 1) >> 2, kc1 = (idx + 1) & 3;
                    ldsm4(kb[cur ^ 1], kb0 + np1 * 16 * AST * 2 + kc1 * 32);
                }
                mmaf16(sacc[np * 2],     qh[kc], kb[cur][0], kb[cur][2]);
                mmaf16(sacc[np * 2 + 1], qh[kc], kb[cur][1], kb[cur][3]);
            }
        }
        __syncthreads();
        if (kt < 15) {
            loadTile(kbh, dsm, (kt + 1) * 128);
            loadTile(vbh, dsm + AARR + (vs ^ 1) * AARR, (kt + 1) * 128);
            CP_COMMIT();
        }

        // ---- online softmax (base-2 units) ----
        float tm0 = -1e30f, tm1 = -1e30f;
#pragma unroll
        for (int nt = 0; nt < 16; nt++) {
            tm0 = fmaxf(tm0, fmaxf(sacc[nt][0], sacc[nt][1]));
            tm1 = fmaxf(tm1, fmaxf(sacc[nt][2], sacc[nt][3]));
        }
        tm0 = fmaxf(tm0, __shfl_xor_sync(0xffffffffu, tm0, 1));
        tm0 = fmaxf(tm0, __shfl_xor_sync(0xffffffffu, tm0, 2));
        tm1 = fmaxf(tm1, __shfl_xor_sync(0xffffffffu, tm1, 1));
        tm1 = fmaxf(tm1, __shfl_xor_sync(0xffffffffu, tm1, 2));

        const float nm0 = fmaxf(mr0, tm0 * C2);
        const float nm1 = fmaxf(mr1, tm1 * C2);
        const float al0 = ex2(mr0 - nm0);
        const float al1 = ex2(mr1 - nm1);
        mr0 = nm0; mr1 = nm1;
#pragma unroll
        for (int nt = 0; nt < 8; nt++) {
            oacc[nt][0] *= al0; oacc[nt][1] *= al0;
            oacc[nt][2] *= al1; oacc[nt][3] *= al1;
        }

        float rs0 = 0.f, rs1 = 0.f;
        uint32_t php[8][4];
#pragma unroll
        for (int j = 0; j < 8; j++) {
            const float p00 = ex2(fmaf(sacc[2 * j][0],     C2, -nm0));
            const float p01 = ex2(fmaf(sacc[2 * j][1],     C2, -nm0));
            const float p10 = ex2(fmaf(sacc[2 * j][2],     C2, -nm1));
            const float p11 = ex2(fmaf(sacc[2 * j][3],     C2, -nm1));
            const float r00 = ex2(fmaf(sacc[2 * j + 1][0], C2, -nm0));
            const float r01 = ex2(fmaf(sacc[2 * j + 1][1], C2, -nm0));
            const float r10 = ex2(fmaf(sacc[2 * j + 1][2], C2, -nm1));
            const float r11 = ex2(fmaf(sacc[2 * j + 1][3], C2, -nm1));
            rs0 += (p00 + p01) + (r00 + r01);
            rs1 += (p10 + p11) + (r10 + r11);
            php[j][0] = pkh(p00, p01);
            php[j][1] = pkh(p10, p11);
            php[j][2] = pkh(r00, r01);
            php[j][3] = pkh(r10, r11);
        }
        rs0 += __shfl_xor_sync(0xffffffffu, rs0, 1);
        rs0 += __shfl_xor_sync(0xffffffffu, rs0, 2);
        rs1 += __shfl_xor_sync(0xffffffffu, rs1, 1);
        rs1 += __shfl_xor_sync(0xffffffffu, rs1, 2);
        lr0 = lr0 * al0 + rs0;
        lr1 = lr1 * al1 + rs1;

        // ---- O += P V ----
        {
            const uint32_t vb0 = su32(dsm + AARR + vs * AARR) + vla;
            uint32_t vb[2][4];
            ldsm4t(vb[0], vb0);
#pragma unroll
            for (int idx = 0; idx < 32; idx++) {
                const int j = idx >> 2, dp = idx & 3;
                const int cur = idx & 1;
                if (idx < 31) {
                    const int j1 = (idx + 1) >> 2, dp1 = (idx + 1) & 3;
                    ldsm4t(vb[cur ^ 1], vb0 + j1 * 16 * AST * 2 + dp1 * 32);
                }
                mmaf16(oacc[dp * 2],     php[j], vb[cur][0], vb[cur][1]);
                mmaf16(oacc[dp * 2 + 1], php[j], vb[cur][2], vb[cur][3]);
            }
        }

        if (kt < 15) { CP_WAIT(0); __syncthreads(); }
    }

    // ---- epilogue: normalize, store fp16 ----
    const float inv0 = 1.f / lr0, inv1 = 1.f / lr1;
    const int g = lane >> 2, tq = lane & 3;
    const size_t r0o = (size_t)(b * T_ + q0 + wid * 16 + g);
#pragma unroll
    for (int nt = 0; nt < 8; nt++) {
        const int col = h * DH_ + nt * 8 + tq * 2;
        *(uint32_t*)&attnh[r0o * D_ + col] =
            pkh(oacc[nt][0] * inv0, oacc[nt][1] * inv0);
        *(uint32_t*)&attnh[(r0o + 8) * D_ + col] =
            pkh(oacc[nt][2] * inv1, oacc[nt][3] * inv1);
    }
}

// ---------------------------------------------------------------------------
// kernel_launch
// ---------------------------------------------------------------------------
extern "C" void kernel_launch(void* const* d_in, const int* in_sizes, int n_in,
                              void* d_out, int out_size)
{
    const float* x     = (const float*)d_in[0];
    const float* w_qkv = (const float*)d_in[1];
    const float* b_qkv = (const float*)d_in[2];
    const float* w_out = (const float*)d_in[3];
    const float* b_out = (const float*)d_in[4];
    float* out = (float*)d_out;

    __half *xh, *wqh, *woh, *qh, *ah;
    cudaGetSymbolAddress((void**)&xh,  g_x_h);
    cudaGetSymbolAddress((void**)&wqh, g_wqkv_h);
    cudaGetSymbolAddress((void**)&woh, g_wout_h);
    cudaGetSymbolAddress((void**)&qh,  g_qkv_h);
    cudaGetSymbolAddress((void**)&ah,  g_attn_h);

    // 0) round inputs to fp16
    presingle<<<1024, 256>>>(x,     xh,  NTOK * D_ / 4);
    presingle<<<1024, 256>>>(w_qkv, wqh, QKV_COLS * D_ / 4);
    presingle<<<512,  256>>>(w_out, woh, D_ * D_ / 4);

    const int gsmem = NSTG * GSTAGE;  // 81920
    cudaFuncSetAttribute(gemm_f16<true>,
                         cudaFuncAttributeMaxDynamicSharedMemorySize, gsmem);
    cudaFuncSetAttribute(gemm_f16<false>,
                         cudaFuncAttributeMaxDynamicSharedMemorySize, gsmem);

    // 1) QKV projection -> fp16
    {
        dim3 grid(QKV_COLS / 128, NTOK / 128);
        gemm_f16<true><<<grid, 128, gsmem>>>(xh, wqh, b_qkv,
                                             nullptr, qh, QKV_COLS, D_);
    }

    // 2) Flash attention -> fp16
    {
        const int asmem = 3 * AARR;  // 55296
        cudaFuncSetAttribute(attn_f16,
                             cudaFuncAttributeMaxDynamicSharedMemorySize, asmem);
        dim3 grid(T_ / 128, B_ * H_);
        attn_f16<<<grid, 256, asmem>>>(qh, ah);
    }

    // 3) Output projection -> fp32
    {
        dim3 grid(D_ / 128, NSTG > 0 ? NTOK / 128 : 0);
        gemm_f16<false><<<grid, 128, gsmem>>>(ah, woh, b_out,
                                              out, nullptr, D_, D_);
    }
}

// round 10
// speedup vs baseline: 1.1754x; 1.0434x over previous
#include <cuda_runtime.h>
#include <cuda_fp16.h>
#include <math.h>
#include <stdint.h>

#define B_   4
#define T_   2048
#define D_   1024
#define H_   16
#define DH_  64
#define NTOK (B_ * T_)          // 8192
#define QKV_COLS (3 * D_)       // 3072

// ---------------------------------------------------------------------------
// fp16 global scratch (allocation-free rule: __device__ globals)
// ---------------------------------------------------------------------------
__device__ __half g_x_h[(size_t)NTOK * D_];
__device__ __half g_wqkv_h[(size_t)QKV_COLS * D_];
__device__ __half g_wout_h[(size_t)D_ * D_];
__device__ __half g_qkv_h[(size_t)NTOK * QKV_COLS];
__device__ __half g_attn_h[(size_t)NTOK * D_];

// ---------------------------------------------------------------------------
// helpers
// ---------------------------------------------------------------------------
__device__ __forceinline__ uint32_t su32(const void* p) {
    return (uint32_t)__cvta_generic_to_shared(p);
}
__device__ __forceinline__ void ldsm4(uint32_t* r, uint32_t a) {
    asm volatile("ldmatrix.sync.aligned.m8n8.x4.shared.b16 {%0,%1,%2,%3}, [%4];"
        : "=r"(r[0]), "=r"(r[1]), "=r"(r[2]), "=r"(r[3]) : "r"(a));
}
__device__ __forceinline__ void ldsm4t(uint32_t* r, uint32_t a) {
    asm volatile("ldmatrix.sync.aligned.m8n8.x4.trans.shared.b16 {%0,%1,%2,%3}, [%4];"
        : "=r"(r[0]), "=r"(r[1]), "=r"(r[2]), "=r"(r[3]) : "r"(a));
}
__device__ __forceinline__ void mmaf16(float* c, const uint32_t* a,
                                       uint32_t b0, uint32_t b1) {
    asm volatile(
        "mma.sync.aligned.m16n8k16.row.col.f32.f16.f16.f32 "
        "{%0,%1,%2,%3},{%4,%5,%6,%7},{%8,%9},{%0,%1,%2,%3};"
        : "+f"(c[0]), "+f"(c[1]), "+f"(c[2]), "+f"(c[3])
        : "r"(a[0]), "r"(a[1]), "r"(a[2]), "r"(a[3]), "r"(b0), "r"(b1));
}
__device__ __forceinline__ uint32_t pkh(float x, float y) {
    __half2 t = __floats2half2_rn(x, y);
    return *reinterpret_cast<uint32_t*>(&t);
}
__device__ __forceinline__ float ex2(float x) {
    float r;
    asm("ex2.approx.f32 %0, %1;" : "=f"(r) : "f"(x));
    return r;
}
// packed half2 exp2: one MUFU for two P values, result already fp16x2
__device__ __forceinline__ uint32_t hex2(uint32_t a) {
    uint32_t r;
    asm("ex2.approx.f16x2 %0, %1;" : "=r"(r) : "r"(a));
    return r;
}
__device__ __forceinline__ float2 h2f2(uint32_t a) {
    __half2 t = *reinterpret_cast<__half2*>(&a);
    return __half22float2(t);
}
__device__ __forceinline__ void cpa16(uint32_t s, const void* g) {
    asm volatile("cp.async.cg.shared.global [%0], [%1], 16;" :: "r"(s), "l"(g));
}
#define CP_COMMIT() asm volatile("cp.async.commit_group;" ::: "memory")
#define CP_WAIT(n)  asm volatile("cp.async.wait_group %0;" :: "n"(n) : "memory")

// ---------------------------------------------------------------------------
// merged presplit: fp32 -> fp16 for x, w_qkv, w_out in one launch
// ---------------------------------------------------------------------------
#define N4_X  (NTOK * D_ / 4)            // 2097152
#define N4_WQ (QKV_COLS * D_ / 4)        // 786432
#define N4_WO (D_ * D_ / 4)              // 262144

__global__ void presingle_all(const float* __restrict__ x,
                              const float* __restrict__ wq,
                              const float* __restrict__ wo,
                              __half* __restrict__ xh,
                              __half* __restrict__ wqh,
                              __half* __restrict__ woh)
{
    const int total = N4_X + N4_WQ + N4_WO;
    int i = blockIdx.x * blockDim.x + threadIdx.x;
    const int stride = gridDim.x * blockDim.x;
    for (; i < total; i += stride) {
        const float* src;
        __half* dst;
        int j = i;
        if (j < N4_X)                { src = x;  dst = xh; }
        else if ((j -= N4_X) < N4_WQ){ src = wq; dst = wqh; }
        else                         { j -= N4_WQ; src = wo; dst = woh; }
        float4 v = ((const float4*)src)[j];
        ((uint2*)dst)[j] = make_uint2(pkh(v.x, v.y), pkh(v.z, v.w));
    }
}

// ---------------------------------------------------------------------------
// fp16 GEMM (unchanged from R9 — at the mma.sync rate ceiling).
// BM=BN=128, BK=32, 128 threads (4 warps 2x2, warp tile 64x64).
// 4-stage cp.async pipeline; fragments double-buffered a FULL kk ahead.
// ---------------------------------------------------------------------------
#define GST 40                       // smem row stride in fp16 (80 bytes)
#define GARR (128 * GST * 2)         // 10240 bytes per array
#define GSTAGE (2 * GARR)            // 20480 bytes per stage
#define NSTG 4

template<bool WRITE_HALF>
__global__ __launch_bounds__(128, 2)
void gemm_f16(const __half* __restrict__ Ahg, const __half* __restrict__ Bhg,
              const float* __restrict__ bias,
              float* __restrict__ Cf, __half* __restrict__ Ch, int Ntot, int K)
{
    extern __shared__ char dsm[];

    const int tid = threadIdx.x, lane = tid & 31, wid = tid >> 5;
    const int wm = wid & 1, wn = wid >> 1;
    const int row0 = blockIdx.y * 128, col0 = blockIdx.x * 128;

    float acc[4][8][4];
#pragma unroll
    for (int mt = 0; mt < 4; mt++)
#pragma unroll
        for (int nt = 0; nt < 8; nt++)
#pragma unroll
            for (int i = 0; i < 4; i++) acc[mt][nt][i] = 0.f;

    auto prefetch = [&](int it) {
        char* base = dsm + (it & (NSTG - 1)) * GSTAGE;
#pragma unroll
        for (int i = 0; i < 4; i++) {
            const int id = tid + i * 128;        // 0..511
            const int r = id >> 2, c = id & 3;
            const uint32_t so = r * 80 + c * 16;
            cpa16(su32(base + so),        Ahg + (size_t)(row0 + r) * K + it * 32 + c * 8);
            cpa16(su32(base + GARR + so), Bhg + (size_t)(col0 + r) * K + it * 32 + c * 8);
        }
    };

    const int nit = K / 32;
#pragma unroll
    for (int it = 0; it < NSTG - 1; it++) { prefetch(it); CP_COMMIT(); }

    const uint32_t la = ((lane & 15) * GST + ((lane >> 4) << 3)) * 2;
    const uint32_t awo = wm * 64 * GST * 2 + la;
    const uint32_t bwo = GARR + wn * 64 * GST * 2 + la;

    CP_WAIT(NSTG - 2);
    __syncthreads();

    uint32_t fa[2][4][4], fb[2][4][4];
    {
        const uint32_t sbase = su32(dsm);
#pragma unroll
        for (int t = 0; t < 4; t++) ldsm4(fa[0][t], sbase + awo + t * 16 * GST * 2);
#pragma unroll
        for (int t = 0; t < 4; t++) ldsm4(fb[0][t], sbase + bwo + t * 16 * GST * 2);
    }

    for (int it = 0; it < nit; it++) {
        const uint32_t sbase = su32(dsm + (it & (NSTG - 1)) * GSTAGE);

#pragma unroll
        for (int t = 0; t < 4; t++) ldsm4(fa[1][t], sbase + awo + t * 16 * GST * 2 + 32);
#pragma unroll
        for (int t = 0; t < 4; t++) ldsm4(fb[1][t], sbase + bwo + t * 16 * GST * 2 + 32);

#pragma unroll
        for (int mt = 0; mt < 4; mt++)
#pragma unroll
            for (int np = 0; np < 4; np++) {
                mmaf16(acc[mt][np * 2],     fa[0][mt], fb[0][np][0], fb[0][np][2]);
                mmaf16(acc[mt][np * 2 + 1], fa[0][mt], fb[0][np][1], fb[0][np][3]);
            }

        if (it + NSTG - 1 < nit) prefetch(it + NSTG - 1);
        CP_COMMIT();
        CP_WAIT(NSTG - 2);
        __syncthreads();

        if (it + 1 < nit) {
            const uint32_t sb2 = su32(dsm + ((it + 1) & (NSTG - 1)) * GSTAGE);
#pragma unroll
            for (int t = 0; t < 4; t++) ldsm4(fa[0][t], sb2 + awo + t * 16 * GST * 2);
#pragma unroll
            for (int t = 0; t < 4; t++) ldsm4(fb[0][t], sb2 + bwo + t * 16 * GST * 2);
        }

#pragma unroll
        for (int mt = 0; mt < 4; mt++)
#pragma unroll
            for (int np = 0; np < 4; np++) {
                mmaf16(acc[mt][np * 2],     fa[1][mt], fb[1][np][0], fb[1][np][2]);
                mmaf16(acc[mt][np * 2 + 1], fa[1][mt], fb[1][np][1], fb[1][np][3]);
            }
    }

    // epilogue
    const int g = lane >> 2, tq = lane & 3;
#pragma unroll
    for (int mt = 0; mt < 4; mt++) {
        const int r = row0 + wm * 64 + mt * 16 + g;
#pragma unroll
        for (int nt = 0; nt < 8; nt++) {
            const int c = col0 + wn * 64 + nt * 8 + tq * 2;
            float2 bi = *(const float2*)(bias + c);
            const float f0 = acc[mt][nt][0] + bi.x, f1 = acc[mt][nt][1] + bi.y;
            const float f2 = acc[mt][nt][2] + bi.x, f3 = acc[mt][nt][3] + bi.y;
            if (WRITE_HALF) {
                *(uint32_t*)&Ch[(size_t)r * Ntot + c]       = pkh(f0, f1);
                *(uint32_t*)&Ch[(size_t)(r + 8) * Ntot + c] = pkh(f2, f3);
            } else {
                *(float2*)(Cf + (size_t)r * Ntot + c)       = make_float2(f0, f1);
                *(float2*)(Cf + (size_t)(r + 8) * Ntot + c) = make_float2(f2, f3);
            }
        }
    }
}

// ---------------------------------------------------------------------------
// Flash attention, fp16, base-2 softmax with packed f16x2 exp2.
// 256 threads (8 warps), 128 q-rows per block, one (b,h).
// ---------------------------------------------------------------------------
#define AST 72
#define AARR (128 * AST * 2)   // 18432 bytes per array
#define C2   0.1803368801f     // (1/sqrt(64)) * log2(e)

__global__ __launch_bounds__(256, 2)
void attn_f16(const __half* __restrict__ qkvh, __half* __restrict__ attnh)
{
    extern __shared__ char dsm[];
    __half* Kh = (__half*)dsm;

    const int tid = threadIdx.x, lane = tid & 31, wid = tid >> 5;
    const int b = blockIdx.y >> 4, h = blockIdx.y & 15;
    const int q0 = blockIdx.x * 128;

    const size_t hb = (size_t)b * T_ * QKV_COLS + h * DH_;
    const __half* qbh = qkvh + hb;
    const __half* kbh = qbh + D_;
    const __half* vbh = qbh + 2 * D_;

    auto loadTile = [&](const __half* src, char* dstbase, int row_off) {
#pragma unroll
        for (int i = 0; i < 4; i++) {
            const int id = tid + i * 256;
            const int r = id >> 3, c = id & 7;
            const uint32_t so = r * 144 + c * 16;
            const size_t g = (size_t)(row_off + r) * QKV_COLS + c * 8;
            cpa16(su32(dstbase + so), src + g);
        }
    };

    // ---- stage Q, pull fragments ----
    loadTile(qbh, dsm, q0);
    CP_COMMIT(); CP_WAIT(0); __syncthreads();

    uint32_t qh[4][4];
#pragma unroll
    for (int kc = 0; kc < 4; kc++) {
        const int rw = wid * 16 + (lane & 15);
        const int cl = kc * 16 + ((lane >> 4) << 3);
        ldsm4(qh[kc], su32(&Kh[rw * AST + cl]));
    }
    __syncthreads();

    loadTile(kbh, dsm, 0);
    loadTile(vbh, dsm + AARR, 0);
    CP_COMMIT(); CP_WAIT(0); __syncthreads();

    float oacc[8][4];
#pragma unroll
    for (int nt = 0; nt < 8; nt++)
#pragma unroll
        for (int i = 0; i < 4; i++) oacc[nt][i] = 0.f;
    float mr0 = -1e30f, mr1 = -1e30f, lr0 = 0.f, lr1 = 0.f;

    const uint32_t kla = (lane & 15) * AST * 2 + ((lane >> 4) << 3) * 2;
    const uint32_t vla = ((lane & 7) + ((lane >> 3) & 1) * 8) * AST * 2 +
                         ((lane >> 4) << 3) * 2;

    for (int kt = 0; kt < 16; kt++) {
        const int vs = kt & 1;

        // ---- S = Q K^T ----
        float sacc[16][4];
#pragma unroll
        for (int nt = 0; nt < 16; nt++)
#pragma unroll
            for (int i = 0; i < 4; i++) sacc[nt][i] = 0.f;

        {
            const uint32_t kb0 = su32(Kh) + kla;
            uint32_t kb[2][4];
            ldsm4(kb[0], kb0);
#pragma unroll
            for (int idx = 0; idx < 32; idx++) {
                const int np = idx >> 2, kc = idx & 3;
                const int cur = idx & 1;
                if (idx < 31) {
                    const int np1 = (idx + 1) >> 2, kc1 = (idx + 1) & 3;
                    ldsm4(kb[cur ^ 1], kb0 + np1 * 16 * AST * 2 + kc1 * 32);
                }
                mmaf16(sacc[np * 2],     qh[kc], kb[cur][0], kb[cur][2]);
                mmaf16(sacc[np * 2 + 1], qh[kc], kb[cur][1], kb[cur][3]);
            }
        }
        __syncthreads();
        if (kt < 15) {
            loadTile(kbh, dsm, (kt + 1) * 128);
            loadTile(vbh, dsm + AARR + (vs ^ 1) * AARR, (kt + 1) * 128);
            CP_COMMIT();
        }

        // ---- online softmax (base-2 units, packed f16x2 exp2) ----
        float tm0 = -1e30f, tm1 = -1e30f;
#pragma unroll
        for (int nt = 0; nt < 16; nt++) {
            tm0 = fmaxf(tm0, fmaxf(sacc[nt][0], sacc[nt][1]));
            tm1 = fmaxf(tm1, fmaxf(sacc[nt][2], sacc[nt][3]));
        }
        tm0 = fmaxf(tm0, __shfl_xor_sync(0xffffffffu, tm0, 1));
        tm0 = fmaxf(tm0, __shfl_xor_sync(0xffffffffu, tm0, 2));
        tm1 = fmaxf(tm1, __shfl_xor_sync(0xffffffffu, tm1, 1));
        tm1 = fmaxf(tm1, __shfl_xor_sync(0xffffffffu, tm1, 2));

        const float nm0 = fmaxf(mr0, tm0 * C2);
        const float nm1 = fmaxf(mr1, tm1 * C2);
        const float al0 = ex2(mr0 - nm0);
        const float al1 = ex2(mr1 - nm1);
        mr0 = nm0; mr1 = nm1;
#pragma unroll
        for (int nt = 0; nt < 8; nt++) {
            oacc[nt][0] *= al0; oacc[nt][1] *= al0;
            oacc[nt][2] *= al1; oacc[nt][3] *= al1;
        }

        float rs0 = 0.f, rs1 = 0.f;
        uint32_t php[8][4];
#pragma unroll
        for (int j = 0; j < 8; j++) {
            // pack base-2 logits to half2, one MUFU per pair; result IS P (fp16x2)
            php[j][0] = hex2(pkh(fmaf(sacc[2 * j][0],     C2, -nm0),
                                 fmaf(sacc[2 * j][1],     C2, -nm0)));
            php[j][1] = hex2(pkh(fmaf(sacc[2 * j][2],     C2, -nm1),
                                 fmaf(sacc[2 * j][3],     C2, -nm1)));
            php[j][2] = hex2(pkh(fmaf(sacc[2 * j + 1][0], C2, -nm0),
                                 fmaf(sacc[2 * j + 1][1], C2, -nm0)));
            php[j][3] = hex2(pkh(fmaf(sacc[2 * j + 1][2], C2, -nm1),
                                 fmaf(sacc[2 * j + 1][3], C2, -nm1)));
            const float2 f0 = h2f2(php[j][0]);
            const float2 f1 = h2f2(php[j][1]);
            const float2 f2 = h2f2(php[j][2]);
            const float2 f3 = h2f2(php[j][3]);
            rs0 += (f0.x + f0.y) + (f2.x + f2.y);
            rs1 += (f1.x + f1.y) + (f3.x + f3.y);
        }
        rs0 += __shfl_xor_sync(0xffffffffu, rs0, 1);
        rs0 += __shfl_xor_sync(0xffffffffu, rs0, 2);
        rs1 += __shfl_xor_sync(0xffffffffu, rs1, 1);
        rs1 += __shfl_xor_sync(0xffffffffu, rs1, 2);
        lr0 = lr0 * al0 + rs0;
        lr1 = lr1 * al1 + rs1;

        // ---- O += P V ----
        {
            const uint32_t vb0 = su32(dsm + AARR + vs * AARR) + vla;
            uint32_t vb[2][4];
            ldsm4t(vb[0], vb0);
#pragma unroll
            for (int idx = 0; idx < 32; idx++) {
                const int j = idx >> 2, dp = idx & 3;
                const int cur = idx & 1;
                if (idx < 31) {
                    const int j1 = (idx + 1) >> 2, dp1 = (idx + 1) & 3;
                    ldsm4t(vb[cur ^ 1], vb0 + j1 * 16 * AST * 2 + dp1 * 32);
                }
                mmaf16(oacc[dp * 2],     php[j], vb[cur][0], vb[cur][1]);
                mmaf16(oacc[dp * 2 + 1], php[j], vb[cur][2], vb[cur][3]);
            }
        }

        if (kt < 15) { CP_WAIT(0); __syncthreads(); }
    }

    // ---- epilogue: normalize, store fp16 ----
    const float inv0 = 1.f / lr0, inv1 = 1.f / lr1;
    const int g = lane >> 2, tq = lane & 3;
    const size_t r0o = (size_t)(b * T_ + q0 + wid * 16 + g);
#pragma unroll
    for (int nt = 0; nt < 8; nt++) {
        const int col = h * DH_ + nt * 8 + tq * 2;
        *(uint32_t*)&attnh[r0o * D_ + col] =
            pkh(oacc[nt][0] * inv0, oacc[nt][1] * inv0);
        *(uint32_t*)&attnh[(r0o + 8) * D_ + col] =
            pkh(oacc[nt][2] * inv1, oacc[nt][3] * inv1);
    }
}

// ---------------------------------------------------------------------------
// kernel_launch
// ---------------------------------------------------------------------------
extern "C" void kernel_launch(void* const* d_in, const int* in_sizes, int n_in,
                              void* d_out, int out_size)
{
    const float* x     = (const float*)d_in[0];
    const float* w_qkv = (const float*)d_in[1];
    const float* b_qkv = (const float*)d_in[2];
    const float* w_out = (const float*)d_in[3];
    const float* b_out = (const float*)d_in[4];
    float* out = (float*)d_out;

    __half *xh, *wqh, *woh, *qh, *ah;
    cudaGetSymbolAddress((void**)&xh,  g_x_h);
    cudaGetSymbolAddress((void**)&wqh, g_wqkv_h);
    cudaGetSymbolAddress((void**)&woh, g_wout_h);
    cudaGetSymbolAddress((void**)&qh,  g_qkv_h);
    cudaGetSymbolAddress((void**)&ah,  g_attn_h);

    // 0) round all inputs to fp16 (single launch)
    presingle_all<<<2048, 256>>>(x, w_qkv, w_out, xh, wqh, woh);

    const int gsmem = NSTG * GSTAGE;  // 81920
    cudaFuncSetAttribute(gemm_f16<true>,
                         cudaFuncAttributeMaxDynamicSharedMemorySize, gsmem);
    cudaFuncSetAttribute(gemm_f16<false>,
                         cudaFuncAttributeMaxDynamicSharedMemorySize, gsmem);

    // 1) QKV projection -> fp16
    {
        dim3 grid(QKV_COLS / 128, NTOK / 128);
        gemm_f16<true><<<grid, 128, gsmem>>>(xh, wqh, b_qkv,
                                             nullptr, qh, QKV_COLS, D_);
    }

    // 2) Flash attention -> fp16
    {
        const int asmem = 3 * AARR;  // 55296
        cudaFuncSetAttribute(attn_f16,
                             cudaFuncAttributeMaxDynamicSharedMemorySize, asmem);
        dim3 grid(T_ / 128, B_ * H_);
        attn_f16<<<grid, 256, asmem>>>(qh, ah);
    }

    // 3) Output projection -> fp32
    {
        dim3 grid(D_ / 128, NTOK / 128);
        gemm_f16<false><<<grid, 128, gsmem>>>(ah, woh, b_out,
                                              out, nullptr, D_, D_);
    }
}